// round 7
// baseline (speedup 1.0000x reference)
#include <cuda_runtime.h>
#include <cuda_bf16.h>
#include <cstdint>
#include <math.h>

// Problem constants
constexpr int BATCH = 4;
constexpr int CH    = 256;
constexpr int SPA   = 4096;
constexpr int NGRP  = 8;
constexpr int CPG   = CH / NGRP;
constexpr int NH    = 4;
constexpr int HD    = CH / NH;    // 64
constexpr float EPS = 1e-5f;
constexpr float SCALE = 0.125f;

constexpr int GRP_ELEMS = CPG * SPA;
constexpr int PARTS = 32;

// Scratch
__device__ __nv_bfloat16 g_xn [(size_t)BATCH * CH  * SPA];
__device__ __nv_bfloat16 g_qkv[(size_t)BATCH * 3*CH * SPA];
__device__ __nv_bfloat16 g_ao [(size_t)BATCH * CH  * SPA];
__device__ uint8_t g_q8[(size_t)BATCH * NH * SPA * HD];  // [bh][s][d] e4m3
__device__ uint8_t g_k8[(size_t)BATCH * NH * SPA * HD];  // [bh][s][d] e4m3
__device__ uint8_t g_v8[(size_t)BATCH * NH * HD * SPA];  // [bh][d][s] e4m3
__device__ float g_part[BATCH * NGRP][PARTS][2];
__device__ float g_mean[BATCH * NGRP];
__device__ float g_rinv[BATCH * NGRP];

// ---------------------------------------------------------------------------
// Helpers
// ---------------------------------------------------------------------------
__device__ __forceinline__ uint32_t smem_u32(const void* p) {
    return (uint32_t)__cvta_generic_to_shared(p);
}
__device__ __forceinline__ uint32_t packbf(float lo, float hi) {
    __nv_bfloat162 t = __floats2bfloat162_rn(lo, hi);
    return *reinterpret_cast<uint32_t*>(&t);
}
// pack two floats -> e4m3x2 (16-bit). First PTX src operand lands in HIGH byte.
__device__ __forceinline__ uint32_t f2e4m3x2(float lo, float hi) {
    uint16_t r;
    asm("cvt.rn.satfinite.e4m3x2.f32 %0, %1, %2;" : "=h"(r) : "f"(hi), "f"(lo));
    return (uint32_t)r;
}
__device__ __forceinline__ float2 bf2f(uint32_t p) {
    return __bfloat1622float2(*reinterpret_cast<const __nv_bfloat162*>(&p));
}

__device__ __forceinline__ void mma_bf16(float* d, const uint32_t* a,
                                         const uint32_t* b) {
    asm volatile(
        "mma.sync.aligned.m16n8k16.row.col.f32.bf16.bf16.f32 "
        "{%0,%1,%2,%3}, {%4,%5,%6,%7}, {%8,%9}, {%0,%1,%2,%3};\n"
        : "+f"(d[0]), "+f"(d[1]), "+f"(d[2]), "+f"(d[3])
        : "r"(a[0]), "r"(a[1]), "r"(a[2]), "r"(a[3]), "r"(b[0]), "r"(b[1]));
}
// fp8 e4m3 mma: m16n8k32, fp32 accum (sm_89+, not arch-feature gated)
__device__ __forceinline__ void mma_e4m3(float* d, const uint32_t* a,
                                         const uint32_t* b) {
    asm volatile(
        "mma.sync.aligned.m16n8k32.row.col.f32.e4m3.e4m3.f32 "
        "{%0,%1,%2,%3}, {%4,%5,%6,%7}, {%8,%9}, {%0,%1,%2,%3};\n"
        : "+f"(d[0]), "+f"(d[1]), "+f"(d[2]), "+f"(d[3])
        : "r"(a[0]), "r"(a[1]), "r"(a[2]), "r"(a[3]), "r"(b[0]), "r"(b[1]));
}
__device__ __forceinline__ void ldsm_x4(uint32_t* r, uint32_t addr) {
    asm volatile("ldmatrix.sync.aligned.m8n8.x4.shared.b16 {%0,%1,%2,%3}, [%4];\n"
                 : "=r"(r[0]), "=r"(r[1]), "=r"(r[2]), "=r"(r[3]) : "r"(addr));
}
__device__ __forceinline__ void ldsm_x4_t(uint32_t* r, uint32_t addr) {
    asm volatile("ldmatrix.sync.aligned.m8n8.x4.trans.shared.b16 {%0,%1,%2,%3}, [%4];\n"
                 : "=r"(r[0]), "=r"(r[1]), "=r"(r[2]), "=r"(r[3]) : "r"(addr));
}
__device__ __forceinline__ void cpa(uint32_t dst, const void* src) {
    asm volatile("cp.async.cg.shared.global [%0], [%1], 16;\n" :: "r"(dst), "l"(src));
}
#define CP_COMMIT() asm volatile("cp.async.commit_group;\n" ::: "memory")
#define CP_WAIT0()  asm volatile("cp.async.wait_group 0;\n" ::: "memory")

// ---------------------------------------------------------------------------
// GroupNorm
// ---------------------------------------------------------------------------
__global__ __launch_bounds__(256) void k_gn_part(const float* __restrict__ x) {
    int part = blockIdx.x & (PARTS - 1);
    int bg   = blockIdx.x / PARTS;
    const float4* base = reinterpret_cast<const float4*>(x + (size_t)bg * GRP_ELEMS)
                         + (size_t)part * (GRP_ELEMS / PARTS / 4);
    const int n4 = GRP_ELEMS / PARTS / 4;
    float s = 0.f, s2 = 0.f;
    for (int i = threadIdx.x; i < n4; i += 256) {
        float4 v = base[i];
        s  += v.x + v.y + v.z + v.w;
        s2 += v.x*v.x + v.y*v.y + v.z*v.z + v.w*v.w;
    }
    __shared__ float sh[16];
    for (int o = 16; o; o >>= 1) {
        s  += __shfl_xor_sync(0xffffffffu, s,  o);
        s2 += __shfl_xor_sync(0xffffffffu, s2, o);
    }
    if ((threadIdx.x & 31) == 0) { int w = threadIdx.x >> 5; sh[w*2] = s; sh[w*2+1] = s2; }
    __syncthreads();
    if (threadIdx.x == 0) {
        float a = 0.f, b = 0.f;
        #pragma unroll
        for (int i = 0; i < 8; i++) { a += sh[i*2]; b += sh[i*2+1]; }
        g_part[bg][part][0] = a; g_part[bg][part][1] = b;
    }
}

__global__ void k_gn_final() {
    int g = threadIdx.x;
    if (g >= BATCH * NGRP) return;
    float s = 0.f, s2 = 0.f;
    #pragma unroll
    for (int p = 0; p < PARTS; p++) { s += g_part[g][p][0]; s2 += g_part[g][p][1]; }
    const float invN = 1.0f / (float)GRP_ELEMS;
    float mean = s * invN;
    float var  = s2 * invN - mean * mean;
    g_mean[g] = mean; g_rinv[g] = rsqrtf(var + EPS);
}

__global__ __launch_bounds__(256) void k_gn_norm(const float* __restrict__ x,
                                                 const float* __restrict__ gamma,
                                                 const float* __restrict__ beta) {
    int idx4 = blockIdx.x * 256 + threadIdx.x;
    if (idx4 >= (BATCH * CH * SPA) / 4) return;
    int idx = idx4 * 4;
    int c  = (idx >> 12) & (CH - 1);
    int bg = idx >> 17;
    float mean = g_mean[bg], rinv = g_rinv[bg];
    float ga = gamma[c] * rinv;
    float be = beta[c] - mean * ga;
    float4 v = reinterpret_cast<const float4*>(x)[idx4];
    uint2 o;
    o.x = packbf(v.x * ga + be, v.y * ga + be);
    o.y = packbf(v.z * ga + be, v.w * ga + be);
    *reinterpret_cast<uint2*>(&g_xn[idx]) = o;
}

// ---------------------------------------------------------------------------
// bf16 mma.sync GEMM (round-5, known good)
// ---------------------------------------------------------------------------
template<bool RESID, typename OT>
__global__ __launch_bounds__(256, 2) void k_gemm(const float* __restrict__ Wm,
                                                 const float* __restrict__ bias,
                                                 const __nv_bfloat16* __restrict__ X,
                                                 OT* __restrict__ Y,
                                                 const float* __restrict__ resid,
                                                 int M) {
    __shared__ __nv_bfloat16 As[128 * 40];
    __shared__ __nv_bfloat16 Bs[32 * 136];

    const int b  = blockIdx.z;
    const int o0 = blockIdx.y * 128;
    const int s0 = blockIdx.x * 128;
    const int tid = threadIdx.x, lane = tid & 31, wid = tid >> 5;
    const int wm = wid & 3, wn = wid >> 2;
    const int lrow = lane & 7, lmat = lane >> 3;
    const __nv_bfloat16* Xb = X + (size_t)b * CH * SPA;

    float acc[2][8][4] = {};

    for (int k0 = 0; k0 < CH; k0 += 32) {
        #pragma unroll
        for (int r = 0; r < 4; r++) {
            int i = tid + r * 256;
            int row = i >> 3, kq = (i & 7) * 4;
            float4 w4 = *reinterpret_cast<const float4*>(
                            Wm + (size_t)(o0 + row) * CH + k0 + kq);
            uint2 wp = {packbf(w4.x, w4.y), packbf(w4.z, w4.w)};
            *reinterpret_cast<uint2*>(&As[row * 40 + kq]) = wp;
        }
        #pragma unroll
        for (int r = 0; r < 2; r++) {
            int i = tid + r * 256;
            int kr = i >> 4, s8 = (i & 15) * 8;
            uint4 xv = *reinterpret_cast<const uint4*>(
                            Xb + (size_t)(k0 + kr) * SPA + s0 + s8);
            *reinterpret_cast<uint4*>(&Bs[kr * 136 + s8]) = xv;
        }
        __syncthreads();

        #pragma unroll
        for (int kk = 0; kk < 32; kk += 16) {
            uint32_t a[2][4];
            #pragma unroll
            for (int mt = 0; mt < 2; mt++) {
                uint32_t ad = smem_u32(&As[(wm*32 + mt*16 + (lmat & 1)*8 + lrow)*40
                                           + kk + (lmat >> 1)*8]);
                ldsm_x4(a[mt], ad);
            }
            #pragma unroll
            for (int ntp = 0; ntp < 8; ntp += 2) {
                uint32_t bf[4];
                uint32_t ad = smem_u32(&Bs[(kk + (lmat & 1)*8 + lrow)*136
                                           + wn*64 + (ntp + (lmat >> 1))*8]);
                ldsm_x4_t(bf, ad);
                #pragma unroll
                for (int mt = 0; mt < 2; mt++) {
                    mma_bf16(acc[mt][ntp],     a[mt], bf);
                    mma_bf16(acc[mt][ntp + 1], a[mt], bf + 2);
                }
            }
        }
        __syncthreads();
    }

    #pragma unroll
    for (int mt = 0; mt < 2; mt++) {
        int row0 = o0 + wm * 32 + mt * 16 + (lane >> 2);
        float bv0 = bias[row0], bv1 = bias[row0 + 8];
        #pragma unroll
        for (int nt = 0; nt < 8; nt++) {
            int col = s0 + wn * 64 + nt * 8 + 2 * (lane & 3);
            size_t off0 = ((size_t)b * M + row0) * SPA + col;
            size_t off1 = ((size_t)b * M + row0 + 8) * SPA + col;
            float r00 = acc[mt][nt][0] + bv0, r01 = acc[mt][nt][1] + bv0;
            float r10 = acc[mt][nt][2] + bv1, r11 = acc[mt][nt][3] + bv1;
            if (RESID) {
                float2 x0 = *reinterpret_cast<const float2*>(&resid[off0]);
                float2 x1 = *reinterpret_cast<const float2*>(&resid[off1]);
                r00 += x0.x; r01 += x0.y; r10 += x1.x; r11 += x1.y;
            }
            if (sizeof(OT) == 2) {
                uint32_t p0 = packbf(r00, r01), p1 = packbf(r10, r11);
                *reinterpret_cast<uint32_t*>(&Y[off0]) = p0;
                *reinterpret_cast<uint32_t*>(&Y[off1]) = p1;
            } else {
                *reinterpret_cast<float2*>(&Y[off0]) = make_float2(r00, r01);
                *reinterpret_cast<float2*>(&Y[off1]) = make_float2(r10, r11);
            }
        }
    }
}

// ---------------------------------------------------------------------------
// Convert to fp8: q,k -> [s][d] e4m3 (transpose); v -> [d][s] e4m3 (straight)
// ---------------------------------------------------------------------------
__global__ __launch_bounds__(256) void k_cvt() {
    const int bh = blockIdx.x;           // b*4+h
    const int s0 = blockIdx.y * 64;
    const int which = blockIdx.z;        // 0=q, 1=k, 2=v
    const int b = bh >> 2, h = bh & 3;
    const int tid = threadIdx.x;

    if (which == 2) {
        const __nv_bfloat16* src = g_qkv + ((size_t)b * 3 * CH + 2 * CH + h * HD) * SPA;
        uint8_t* dst = g_v8 + (size_t)bh * HD * SPA;
        int d = tid >> 2, so = (tid & 3) * 16;
        const uint32_t* s32 = reinterpret_cast<const uint32_t*>(src + (size_t)d * SPA + s0 + so);
        uint32_t w[4];
        #pragma unroll
        for (int j = 0; j < 4; j++) {
            float2 f0 = bf2f(s32[2*j]), f1 = bf2f(s32[2*j + 1]);
            w[j] = f2e4m3x2(f0.x, f0.y) | (f2e4m3x2(f1.x, f1.y) << 16);
        }
        *reinterpret_cast<uint4*>(dst + (size_t)d * SPA + s0 + so) =
            make_uint4(w[0], w[1], w[2], w[3]);
        return;
    }

    const __nv_bfloat16* src = g_qkv
        + ((size_t)b * 3 * CH + which * CH + h * HD) * SPA;
    uint8_t* dst = (which ? g_k8 : g_q8) + (size_t)bh * SPA * HD;

    __shared__ uint16_t t[64][72];
    {
        int d = tid >> 2, so = (tid & 3) * 16;
        #pragma unroll
        for (int u = 0; u < 2; u++) {
            uint4 v = *reinterpret_cast<const uint4*>(src + (size_t)d * SPA + s0 + so + u*8);
            *reinterpret_cast<uint4*>(&t[d][so + u*8]) = v;
        }
    }
    __syncthreads();
    {
        int s = tid >> 2, doff = (tid & 3) * 16;
        uint32_t w[4];
        #pragma unroll
        for (int j = 0; j < 4; j++) {
            uint32_t p0 = (uint32_t)t[doff + 4*j    ][s] | ((uint32_t)t[doff + 4*j + 1][s] << 16);
            uint32_t p1 = (uint32_t)t[doff + 4*j + 2][s] | ((uint32_t)t[doff + 4*j + 3][s] << 16);
            float2 f0 = bf2f(p0), f1 = bf2f(p1);
            w[j] = f2e4m3x2(f0.x, f0.y) | (f2e4m3x2(f1.x, f1.y) << 16);
        }
        *reinterpret_cast<uint4*>(dst + (size_t)(s0 + s) * HD + doff) =
            make_uint4(w[0], w[1], w[2], w[3]);
    }
}

// ---------------------------------------------------------------------------
// Flash attention, fp8 e4m3 mma (m16n8k32). Warp owns 16 q rows x full keys.
// Q [q][d], K [key][d], V [d][key] in SMEM (stride 80B, conflict-free).
// ---------------------------------------------------------------------------
constexpr int QT = 128;
constexpr int KT = 64;
constexpr int RS = 80;   // SMEM row stride bytes

__global__ __launch_bounds__(256, 2) void k_attn() {
    __shared__ uint8_t Qs[128 * RS];
    __shared__ uint8_t Ks[2][64 * RS];
    __shared__ uint8_t Vs[2][64 * RS];

    const int bh = blockIdx.y, b = bh >> 2, h = bh & 3;
    const int q0 = blockIdx.x * QT;
    const int tid = threadIdx.x, lane = tid & 31, w = tid >> 5;
    const uint32_t c = lane & 3;

    const uint8_t* q8 = g_q8 + ((size_t)bh * SPA + q0) * HD;
    const uint8_t* k8 = g_k8 + (size_t)bh * SPA * HD;
    const uint8_t* v8 = g_v8 + (size_t)bh * HD * SPA;

    const uint32_t qs_a = smem_u32(Qs);
    const uint32_t ks_a[2] = { smem_u32(Ks[0]), smem_u32(Ks[1]) };
    const uint32_t vs_a[2] = { smem_u32(Vs[0]), smem_u32(Vs[1]) };

    // prologue: Q (512 chunks) + K0/V0 (256 each)
    #pragma unroll
    for (int r = 0; r < 2; r++) {
        int i = tid + r * 256;
        int row = i >> 2, ch = (i & 3) * 16;
        cpa(qs_a + row * RS + ch, q8 + row * HD + ch);
    }
    {
        int row = tid >> 2, ch = (tid & 3) * 16;
        if (tid < 256) {
            cpa(ks_a[0] + row * RS + ch, k8 + (size_t)row * HD + ch);
            cpa(vs_a[0] + row * RS + ch, v8 + (size_t)row * SPA + ch);
        }
    }
    CP_COMMIT(); CP_WAIT0();
    __syncthreads();

    // hoist Q A-fragments: kstep s in {0,1} covers d 32s..32s+31
    const int rq = w * 16 + (lane >> 2);
    uint32_t qa[2][4];
    #pragma unroll
    for (int s = 0; s < 2; s++) {
        const uint8_t* r0p = &Qs[rq * RS + c * 4 + 32 * s];
        const uint8_t* r1p = &Qs[(rq + 8) * RS + c * 4 + 32 * s];
        qa[s][0] = *reinterpret_cast<const uint32_t*>(r0p);
        qa[s][1] = *reinterpret_cast<const uint32_t*>(r1p);
        qa[s][2] = *reinterpret_cast<const uint32_t*>(r0p + 16);
        qa[s][3] = *reinterpret_cast<const uint32_t*>(r1p + 16);
    }

    float m2[2] = {-INFINITY, -INFINITY};
    float l [2] = {0.f, 0.f};
    float o_acc[8][4] = {};
    const float CF = SCALE * 1.44269504f;
    const uint32_t lh = lane & ~3u;
    const uint32_t l0 = lh + 2 * (c & 1);
    const bool hi_blk = (c >> 1) != 0;

    for (int t0 = 0; t0 < SPA; t0 += KT) {
        const int i = t0 / KT;
        if (i > 0) { CP_WAIT0(); __syncthreads(); }

        // prefetch tile i+1
        if (t0 + KT < SPA) {
            int bb = (i + 1) & 1;
            int row = tid >> 2, ch = (tid & 3) * 16;
            cpa(ks_a[bb] + row * RS + ch, k8 + (size_t)(t0 + KT + row) * HD + ch);
            cpa(vs_a[bb] + row * RS + ch, v8 + (size_t)row * SPA + t0 + KT + ch);
            CP_COMMIT();
        }

        const uint8_t* Kb = Ks[i & 1];
        const uint8_t* Vb = Vs[i & 1];

        // S = Q K^T  (M=16 q, N=64 keys, K=64 d; 2 k32-steps x 8 n-blocks)
        float sacc[8][4] = {};
        #pragma unroll
        for (int s = 0; s < 2; s++) {
            #pragma unroll
            for (int nt = 0; nt < 8; nt++) {
                const uint8_t* kp = &Kb[(nt * 8 + (lane >> 2)) * RS + c * 4 + 32 * s];
                uint32_t bf[2] = { *reinterpret_cast<const uint32_t*>(kp),
                                   *reinterpret_cast<const uint32_t*>(kp + 16) };
                mma_e4m3(sacc[nt], qa[s], bf);
            }
        }

        // online softmax (per-warp complete rows); p values overwrite sacc
        #pragma unroll
        for (int rh = 0; rh < 2; rh++) {
            float mx = -1e30f;
            #pragma unroll
            for (int nt = 0; nt < 8; nt++)
                mx = fmaxf(mx, fmaxf(sacc[nt][rh*2], sacc[nt][rh*2+1]));
            mx *= CF;
            mx = fmaxf(mx, __shfl_xor_sync(0xffffffffu, mx, 1));
            mx = fmaxf(mx, __shfl_xor_sync(0xffffffffu, mx, 2));
            float mnew = fmaxf(m2[rh], mx);
            float alpha = exp2f(m2[rh] - mnew);
            m2[rh] = mnew;
            float rs = 0.f;
            #pragma unroll
            for (int nt = 0; nt < 8; nt++) {
                float p0 = exp2f(sacc[nt][rh*2]   * CF - mnew);
                float p1 = exp2f(sacc[nt][rh*2+1] * CF - mnew);
                rs += p0 + p1;
                sacc[nt][rh*2] = p0; sacc[nt][rh*2+1] = p1;
                o_acc[nt][rh*2]   *= alpha;
                o_acc[nt][rh*2+1] *= alpha;
            }
            rs += __shfl_xor_sync(0xffffffffu, rs, 1);
            rs += __shfl_xor_sync(0xffffffffu, rs, 2);
            l[rh] = l[rh] * alpha + rs;
        }

        // pack P: P32[nt] = e4m3x2(row0 pair) | e4m3x2(row1 pair) << 16
        uint32_t P32[8];
        #pragma unroll
        for (int nt = 0; nt < 8; nt++)
            P32[nt] = f2e4m3x2(sacc[nt][0], sacc[nt][1])
                    | (f2e4m3x2(sacc[nt][2], sacc[nt][3]) << 16);

        // O += P V  (2 k32-steps over keys x 8 d-blocks)
        #pragma unroll
        for (int g = 0; g < 2; g++) {
            // repack A-fragment for keys 32g..32g+31 via lane-pair shuffles
            uint32_t v00 = __shfl_sync(0xffffffffu, P32[4*g + 0], l0);
            uint32_t v01 = __shfl_sync(0xffffffffu, P32[4*g + 1], l0);
            uint32_t v02 = __shfl_sync(0xffffffffu, P32[4*g + 2], l0);
            uint32_t v03 = __shfl_sync(0xffffffffu, P32[4*g + 3], l0);
            uint32_t v10 = __shfl_sync(0xffffffffu, P32[4*g + 0], l0 + 1);
            uint32_t v11 = __shfl_sync(0xffffffffu, P32[4*g + 1], l0 + 1);
            uint32_t v12 = __shfl_sync(0xffffffffu, P32[4*g + 2], l0 + 1);
            uint32_t v13 = __shfl_sync(0xffffffffu, P32[4*g + 3], l0 + 1);
            uint32_t u0 = hi_blk ? v01 : v00;
            uint32_t u1 = hi_blk ? v11 : v10;
            uint32_t u2 = hi_blk ? v03 : v02;
            uint32_t u3 = hi_blk ? v13 : v12;
            uint32_t aP[4];
            aP[0] = (u0 & 0xFFFFu) | (u1 << 16);
            aP[1] = (u0 >> 16)     | (u1 & 0xFFFF0000u);
            aP[2] = (u2 & 0xFFFFu) | (u3 << 16);
            aP[3] = (u2 >> 16)     | (u3 & 0xFFFF0000u);
            #pragma unroll
            for (int dt = 0; dt < 8; dt++) {
                const uint8_t* vp = &Vb[(dt * 8 + (lane >> 2)) * RS + c * 4 + 32 * g];
                uint32_t bv[2] = { *reinterpret_cast<const uint32_t*>(vp),
                                   *reinterpret_cast<const uint32_t*>(vp + 16) };
                mma_e4m3(o_acc[dt], aP, bv);
            }
        }
    }

    // normalize + write bf16: g_ao[b][h*64+dd][q0+qr]
    __nv_bfloat16* ob = g_ao + ((size_t)b * CH + h * HD) * SPA + q0;
    #pragma unroll
    for (int rh = 0; rh < 2; rh++) {
        float inv = 1.0f / l[rh];
        int qr = w * 16 + rh * 8 + (lane >> 2);
        #pragma unroll
        for (int nt = 0; nt < 8; nt++) {
            int dd = nt * 8 + 2 * (lane & 3);
            ob[(size_t)dd * SPA + qr]       = __float2bfloat16(o_acc[nt][rh*2]   * inv);
            ob[(size_t)(dd + 1) * SPA + qr] = __float2bfloat16(o_acc[nt][rh*2+1] * inv);
        }
    }
}

// ---------------------------------------------------------------------------
extern "C" void kernel_launch(void* const* d_in, const int* in_sizes, int n_in,
                              void* d_out, int out_size) {
    const float* x      = (const float*)d_in[0];
    const float* gamma  = (const float*)d_in[1];
    const float* beta   = (const float*)d_in[2];
    const float* w_qkv  = (const float*)d_in[3];
    const float* b_qkv  = (const float*)d_in[4];
    const float* w_proj = (const float*)d_in[5];
    const float* b_proj = (const float*)d_in[6];
    float* out = (float*)d_out;

    __nv_bfloat16 *xn_p, *qkv_p, *ao_p;
    cudaGetSymbolAddress((void**)&xn_p,  g_xn);
    cudaGetSymbolAddress((void**)&qkv_p, g_qkv);
    cudaGetSymbolAddress((void**)&ao_p,  g_ao);

    // GroupNorm
    k_gn_part <<<BATCH * NGRP * PARTS, 256>>>(x);
    k_gn_final<<<1, 32>>>();
    k_gn_norm <<<(BATCH * CH * SPA) / 4 / 256, 256>>>(x, gamma, beta);

    // QKV GEMM (M = 768), bf16 out
    {
        dim3 grid(SPA / 128, (3 * CH) / 128, BATCH);
        k_gemm<false, __nv_bfloat16><<<grid, 256>>>(w_qkv, b_qkv, xn_p, qkv_p,
                                                    nullptr, 3 * CH);
    }

    // Convert q,k (transpose to [s][d]) and v ([d][s]) to e4m3
    {
        dim3 grid(BATCH * NH, SPA / 64, 3);
        k_cvt<<<grid, 256>>>();
    }

    // fp8 flash attention
    {
        dim3 grid(SPA / QT, BATCH * NH);
        k_attn<<<grid, 256>>>();
    }

    // Proj GEMM + residual (M = 256), fp32 out
    {
        dim3 grid(SPA / 128, CH / 128, BATCH);
        k_gemm<true, float><<<grid, 256>>>(w_proj, b_proj, ao_p, out, x, CH);
    }
}

// round 8
// speedup vs baseline: 1.2840x; 1.2840x over previous
#include <cuda_runtime.h>
#include <cuda_fp16.h>
#include <cstdint>
#include <math.h>

// Problem constants
constexpr int BATCH = 4;
constexpr int CH    = 256;
constexpr int SPA   = 4096;
constexpr int NGRP  = 8;
constexpr int CPG   = CH / NGRP;
constexpr int NH    = 4;
constexpr int HD    = CH / NH;    // 64
constexpr float EPS = 1e-5f;
constexpr float SCALE = 0.125f;

constexpr int GRP_ELEMS = CPG * SPA;
constexpr int PARTS = 32;

// Scratch
__device__ __half g_qkv[(size_t)BATCH * 3*CH * SPA];  // 24 MB
__device__ __half g_ao [(size_t)BATCH * CH  * SPA];   // 8 MB
__device__ float g_part[BATCH * NGRP][PARTS][2];
__device__ float g_ga[BATCH * CH];
__device__ float g_be[BATCH * CH];

// ---------------------------------------------------------------------------
// Helpers
// ---------------------------------------------------------------------------
__device__ __forceinline__ uint32_t smem_u32(const void* p) {
    return (uint32_t)__cvta_generic_to_shared(p);
}
__device__ __forceinline__ uint32_t packh(float lo, float hi) {
    __half2 t = __floats2half2_rn(lo, hi);   // .x = lo = low 16 bits
    return *reinterpret_cast<uint32_t*>(&t);
}
__device__ __forceinline__ uint32_t h2exp2(uint32_t a) {
    uint32_t r;
    asm("ex2.approx.f16x2 %0, %1;" : "=r"(r) : "r"(a));
    return r;
}
__device__ __forceinline__ void mma_f16(float* d, const uint32_t* a,
                                        const uint32_t* b) {
    asm volatile(
        "mma.sync.aligned.m16n8k16.row.col.f32.f16.f16.f32 "
        "{%0,%1,%2,%3}, {%4,%5,%6,%7}, {%8,%9}, {%0,%1,%2,%3};\n"
        : "+f"(d[0]), "+f"(d[1]), "+f"(d[2]), "+f"(d[3])
        : "r"(a[0]), "r"(a[1]), "r"(a[2]), "r"(a[3]), "r"(b[0]), "r"(b[1]));
}
__device__ __forceinline__ void ldsm_x4(uint32_t* r, uint32_t addr) {
    asm volatile("ldmatrix.sync.aligned.m8n8.x4.shared.b16 {%0,%1,%2,%3}, [%4];\n"
                 : "=r"(r[0]), "=r"(r[1]), "=r"(r[2]), "=r"(r[3]) : "r"(addr));
}
__device__ __forceinline__ void ldsm_x4_t(uint32_t* r, uint32_t addr) {
    asm volatile("ldmatrix.sync.aligned.m8n8.x4.trans.shared.b16 {%0,%1,%2,%3}, [%4];\n"
                 : "=r"(r[0]), "=r"(r[1]), "=r"(r[2]), "=r"(r[3]) : "r"(addr));
}
__device__ __forceinline__ void cpa(uint32_t dst, const void* src) {
    asm volatile("cp.async.cg.shared.global [%0], [%1], 16;\n" :: "r"(dst), "l"(src));
}
#define CP_COMMIT() asm volatile("cp.async.commit_group;\n" ::: "memory")
#define CP_WAIT0()  asm volatile("cp.async.wait_group 0;\n" ::: "memory")
#define CP_WAIT1()  asm volatile("cp.async.wait_group 1;\n" ::: "memory")

// ---------------------------------------------------------------------------
// GroupNorm stats
// ---------------------------------------------------------------------------
__global__ __launch_bounds__(256) void k_gn_part(const float* __restrict__ x) {
    int part = blockIdx.x & (PARTS - 1);
    int bg   = blockIdx.x / PARTS;
    const float4* base = reinterpret_cast<const float4*>(x + (size_t)bg * GRP_ELEMS)
                         + (size_t)part * (GRP_ELEMS / PARTS / 4);
    const int n4 = GRP_ELEMS / PARTS / 4;
    float s = 0.f, s2 = 0.f;
    for (int i = threadIdx.x; i < n4; i += 256) {
        float4 v = base[i];
        s  += v.x + v.y + v.z + v.w;
        s2 += v.x*v.x + v.y*v.y + v.z*v.z + v.w*v.w;
    }
    __shared__ float sh[16];
    for (int o = 16; o; o >>= 1) {
        s  += __shfl_xor_sync(0xffffffffu, s,  o);
        s2 += __shfl_xor_sync(0xffffffffu, s2, o);
    }
    if ((threadIdx.x & 31) == 0) { int w = threadIdx.x >> 5; sh[w*2] = s; sh[w*2+1] = s2; }
    __syncthreads();
    if (threadIdx.x == 0) {
        float a = 0.f, b = 0.f;
        #pragma unroll
        for (int i = 0; i < 8; i++) { a += sh[i*2]; b += sh[i*2+1]; }
        g_part[bg][part][0] = a; g_part[bg][part][1] = b;
    }
}

// finalize stats + per-(b,c) GN coefficients (ga, be)
__global__ __launch_bounds__(1024) void k_gn_final(const float* __restrict__ gamma,
                                                   const float* __restrict__ beta) {
    __shared__ float sm_m[32], sm_r[32];
    int t = threadIdx.x;
    if (t < BATCH * NGRP) {
        float s = 0.f, s2 = 0.f;
        #pragma unroll
        for (int p = 0; p < PARTS; p++) { s += g_part[t][p][0]; s2 += g_part[t][p][1]; }
        const float invN = 1.0f / (float)GRP_ELEMS;
        float mean = s * invN;
        float var  = s2 * invN - mean * mean;
        sm_m[t] = mean; sm_r[t] = rsqrtf(var + EPS);
    }
    __syncthreads();
    if (t < BATCH * CH) {
        int b = t >> 8, c = t & 255;
        int bg = b * NGRP + (c >> 5);
        float ga = gamma[c] * sm_r[bg];
        g_ga[t] = ga;
        g_be[t] = beta[c] - sm_m[bg] * ga;
    }
}

// ---------------------------------------------------------------------------
// f16 mma GEMM: Y[b][o][s] = sum_c W[o][c]*X[b][c][s] + bias (+resid)
// GN=true: X is fp32 `x`, normalized on the fly via g_ga/g_be.
// GN=false: X is __half (g_ao).
// ---------------------------------------------------------------------------
template<bool GN, bool RESID, typename OT>
__global__ __launch_bounds__(256, 2) void k_gemm(const float* __restrict__ Wm,
                                                 const float* __restrict__ bias,
                                                 const void* __restrict__ Xv,
                                                 OT* __restrict__ Y,
                                                 const float* __restrict__ resid,
                                                 int M) {
    __shared__ __half As[128 * 40];
    __shared__ __half Bs[32 * 136];

    const int b  = blockIdx.z;
    const int o0 = blockIdx.y * 128;
    const int s0 = blockIdx.x * 128;
    const int tid = threadIdx.x, lane = tid & 31, wid = tid >> 5;
    const int wm = wid & 3, wn = wid >> 2;
    const int lrow = lane & 7, lmat = lane >> 3;

    float acc[2][8][4] = {};

    for (int k0 = 0; k0 < CH; k0 += 32) {
        // A: W tile fp32 -> f16
        #pragma unroll
        for (int r = 0; r < 4; r++) {
            int i = tid + r * 256;
            int row = i >> 3, kq = (i & 7) * 4;
            float4 w4 = *reinterpret_cast<const float4*>(
                            Wm + (size_t)(o0 + row) * CH + k0 + kq);
            uint2 wp = {packh(w4.x, w4.y), packh(w4.z, w4.w)};
            *reinterpret_cast<uint2*>(&As[row * 40 + kq]) = wp;
        }
        // B tile
        #pragma unroll
        for (int r = 0; r < 2; r++) {
            int i = tid + r * 256;
            int kr = i >> 4, s8 = (i & 15) * 8;
            if (GN) {
                const float* Xb = (const float*)Xv + (size_t)b * CH * SPA;
                const float* xp = Xb + (size_t)(k0 + kr) * SPA + s0 + s8;
                float ga = g_ga[b * CH + k0 + kr];
                float be = g_be[b * CH + k0 + kr];
                float4 x0 = *reinterpret_cast<const float4*>(xp);
                float4 x1 = *reinterpret_cast<const float4*>(xp + 4);
                uint4 wv;
                wv.x = packh(x0.x*ga+be, x0.y*ga+be);
                wv.y = packh(x0.z*ga+be, x0.w*ga+be);
                wv.z = packh(x1.x*ga+be, x1.y*ga+be);
                wv.w = packh(x1.z*ga+be, x1.w*ga+be);
                *reinterpret_cast<uint4*>(&Bs[kr * 136 + s8]) = wv;
            } else {
                const __half* Xb = (const __half*)Xv + (size_t)b * CH * SPA;
                uint4 xv = *reinterpret_cast<const uint4*>(
                                Xb + (size_t)(k0 + kr) * SPA + s0 + s8);
                *reinterpret_cast<uint4*>(&Bs[kr * 136 + s8]) = xv;
            }
        }
        __syncthreads();

        #pragma unroll
        for (int kk = 0; kk < 32; kk += 16) {
            uint32_t a[2][4];
            #pragma unroll
            for (int mt = 0; mt < 2; mt++) {
                uint32_t ad = smem_u32(&As[(wm*32 + mt*16 + (lmat & 1)*8 + lrow)*40
                                           + kk + (lmat >> 1)*8]);
                ldsm_x4(a[mt], ad);
            }
            #pragma unroll
            for (int ntp = 0; ntp < 8; ntp += 2) {
                uint32_t bf[4];
                uint32_t ad = smem_u32(&Bs[(kk + (lmat & 1)*8 + lrow)*136
                                           + wn*64 + (ntp + (lmat >> 1))*8]);
                ldsm_x4_t(bf, ad);
                #pragma unroll
                for (int mt = 0; mt < 2; mt++) {
                    mma_f16(acc[mt][ntp],     a[mt], bf);
                    mma_f16(acc[mt][ntp + 1], a[mt], bf + 2);
                }
            }
        }
        __syncthreads();
    }

    #pragma unroll
    for (int mt = 0; mt < 2; mt++) {
        int row0 = o0 + wm * 32 + mt * 16 + (lane >> 2);
        float bv0 = bias[row0], bv1 = bias[row0 + 8];
        #pragma unroll
        for (int nt = 0; nt < 8; nt++) {
            int col = s0 + wn * 64 + nt * 8 + 2 * (lane & 3);
            size_t off0 = ((size_t)b * M + row0) * SPA + col;
            size_t off1 = ((size_t)b * M + row0 + 8) * SPA + col;
            float r00 = acc[mt][nt][0] + bv0, r01 = acc[mt][nt][1] + bv0;
            float r10 = acc[mt][nt][2] + bv1, r11 = acc[mt][nt][3] + bv1;
            if (RESID) {
                float2 x0 = *reinterpret_cast<const float2*>(&resid[off0]);
                float2 x1 = *reinterpret_cast<const float2*>(&resid[off1]);
                r00 += x0.x; r01 += x0.y; r10 += x1.x; r11 += x1.y;
            }
            if (sizeof(OT) == 2) {
                uint32_t p0 = packh(r00, r01), p1 = packh(r10, r11);
                *reinterpret_cast<uint32_t*>(&Y[off0]) = p0;
                *reinterpret_cast<uint32_t*>(&Y[off1]) = p1;
            } else {
                *reinterpret_cast<float2*>(&Y[off0]) = make_float2(r00, r01);
                *reinterpret_cast<float2*>(&Y[off1]) = make_float2(r10, r11);
            }
        }
    }
}

// ---------------------------------------------------------------------------
// Flash attention, f16 mma + ldmatrix, cp.async double-buffered K/V.
// Block = (b,h) x 128 queries; warp w owns q rows [w*16, w*16+16), full keys.
// Q/K/V in [d][*] SMEM layout.
// ---------------------------------------------------------------------------
constexpr int QT = 128;
constexpr int KT = 64;
constexpr int NTILE = SPA / KT;   // 64
constexpr int QS_STR = 136;       // halves
constexpr int KV_STR = 72;        // halves

constexpr int SM_Q  = 0;                       // 64*136*2 = 17408
constexpr int SM_K0 = 17408;                   // 64*72*2  = 9216
constexpr int SM_K1 = SM_K0 + 9216;
constexpr int SM_V0 = SM_K1 + 9216;
constexpr int SM_V1 = SM_V0 + 9216;
constexpr int SM_ATTN = SM_V1 + 9216;          // 54272

__global__ __launch_bounds__(256, 2) void k_attn() {
    extern __shared__ uint8_t smraw[];
    __half* Qs = reinterpret_cast<__half*>(smraw + SM_Q);
    __half* Ks[2] = { reinterpret_cast<__half*>(smraw + SM_K0),
                      reinterpret_cast<__half*>(smraw + SM_K1) };
    __half* Vs[2] = { reinterpret_cast<__half*>(smraw + SM_V0),
                      reinterpret_cast<__half*>(smraw + SM_V1) };

    const int bh = blockIdx.y, b = bh >> 2, h = bh & 3;
    const __half* qb = g_qkv + ((size_t)b * 3 * CH + h * HD) * SPA;
    const __half* kb = qb + (size_t)CH * SPA;
    const __half* vb = qb + (size_t)2 * CH * SPA;
    const int q0 = blockIdx.x * QT;
    const int tid = threadIdx.x, lane = tid & 31, w = tid >> 5;
    const int lrow = lane & 7, lmat = lane >> 3;

    const uint32_t qs_a = smem_u32(Qs);
    const uint32_t ks_a[2] = { smem_u32(Ks[0]), smem_u32(Ks[1]) };
    const uint32_t vs_a[2] = { smem_u32(Vs[0]), smem_u32(Vs[1]) };

    // prologue: Q + K0/V0 (group A), K1/V1 (group B)
    #pragma unroll
    for (int r = 0; r < 4; r++) {           // Q: 1024 chunks of 16B
        int i = tid + r * 256;
        int dd = i >> 4, q8 = (i & 15) * 8;
        cpa(qs_a + (dd * QS_STR + q8) * 2, qb + (size_t)dd * SPA + q0 + q8);
    }
    #pragma unroll
    for (int r = 0; r < 2; r++) {           // K0 + V0: 512 chunks each
        int i = tid + r * 256;
        int dd = i >> 3, k8 = (i & 7) * 8;
        cpa(ks_a[0] + (dd * KV_STR + k8) * 2, kb + (size_t)dd * SPA + k8);
        cpa(vs_a[0] + (dd * KV_STR + k8) * 2, vb + (size_t)dd * SPA + k8);
    }
    CP_COMMIT();
    #pragma unroll
    for (int r = 0; r < 2; r++) {
        int i = tid + r * 256;
        int dd = i >> 3, k8 = (i & 7) * 8;
        cpa(ks_a[1] + (dd * KV_STR + k8) * 2, kb + (size_t)dd * SPA + KT + k8);
        cpa(vs_a[1] + (dd * KV_STR + k8) * 2, vb + (size_t)dd * SPA + KT + k8);
    }
    CP_COMMIT();
    CP_WAIT1();           // Q + tile0 ready
    __syncthreads();

    // hoist Q A-fragments
    uint32_t qa[4][4];
    #pragma unroll
    for (int kk4 = 0; kk4 < 4; kk4++) {
        uint32_t ad = smem_u32(&Qs[(kk4*16 + (lmat >> 1)*8 + lrow) * QS_STR
                                   + w*16 + (lmat & 1)*8]);
        ldsm_x4_t(qa[kk4], ad);
    }

    float m2[2] = {-INFINITY, -INFINITY};
    float l [2] = {0.f, 0.f};
    float o_acc[8][4] = {};
    const float CF = SCALE * 1.44269504f;

    for (int i = 0; i < NTILE; i++) {
        const __half* Kb = Ks[i & 1];
        const __half* Vb = Vs[i & 1];

        // S = Q K^T
        float sacc[8][4] = {};
        #pragma unroll
        for (int kk4 = 0; kk4 < 4; kk4++) {
            #pragma unroll
            for (int ntp = 0; ntp < 8; ntp += 2) {
                uint32_t bf[4];
                uint32_t ad = smem_u32(&Kb[(kk4*16 + (lmat & 1)*8 + lrow) * KV_STR
                                           + (ntp + (lmat >> 1))*8]);
                ldsm_x4_t(bf, ad);
                mma_f16(sacc[ntp],     qa[kk4], bf);
                mma_f16(sacc[ntp + 1], qa[kk4], bf + 2);
            }
        }

        // online softmax: p as f16x2 via ex2.approx.f16x2 (= PV A-frag regs)
        uint32_t pp[8][2];
        #pragma unroll
        for (int rh = 0; rh < 2; rh++) {
            float mx = -1e30f;
            #pragma unroll
            for (int nt = 0; nt < 8; nt++)
                mx = fmaxf(mx, fmaxf(sacc[nt][rh*2], sacc[nt][rh*2+1]));
            mx *= CF;
            mx = fmaxf(mx, __shfl_xor_sync(0xffffffffu, mx, 1));
            mx = fmaxf(mx, __shfl_xor_sync(0xffffffffu, mx, 2));
            float mnew = fmaxf(m2[rh], mx);
            __half2 sum2 = __floats2half2_rn(0.f, 0.f);
            #pragma unroll
            for (int nt = 0; nt < 8; nt++) {
                uint32_t sp = packh(sacc[nt][rh*2]   * CF - mnew,
                                    sacc[nt][rh*2+1] * CF - mnew);
                uint32_t ph = h2exp2(sp);
                pp[nt][rh] = ph;
                sum2 = __hadd2(sum2, *reinterpret_cast<__half2*>(&ph));
            }
            float2 sf = __half22float2(sum2);
            float rs = sf.x + sf.y;
            rs += __shfl_xor_sync(0xffffffffu, rs, 1);
            rs += __shfl_xor_sync(0xffffffffu, rs, 2);
            if (mx > m2[rh]) {          // max moved: rescale
                float alpha = exp2f(m2[rh] - mnew);
                #pragma unroll
                for (int nt = 0; nt < 8; nt++) {
                    o_acc[nt][rh*2]   *= alpha;
                    o_acc[nt][rh*2+1] *= alpha;
                }
                l[rh] = l[rh] * alpha + rs;
                m2[rh] = mnew;
            } else {
                l[rh] += rs;
            }
        }

        // O += P V
        #pragma unroll
        for (int j = 0; j < 4; j++) {
            uint32_t pa[4] = {pp[2*j][0], pp[2*j][1], pp[2*j+1][0], pp[2*j+1][1]};
            #pragma unroll
            for (int dt = 0; dt < 8; dt += 2) {
                uint32_t bv[4];
                uint32_t ad = smem_u32(&Vb[((dt + (lmat >> 1))*8 + lrow) * KV_STR
                                           + j*16 + (lmat & 1)*8]);
                ldsm_x4(bv, ad);
                mma_f16(o_acc[dt],     pa, bv);
                mma_f16(o_acc[dt + 1], pa, bv + 2);
            }
        }

        // rotate buffers: done reading buf[i&1]; prefetch tile i+2 into it
        __syncthreads();
        if (i + 2 < NTILE) {
            int t0 = (i + 2) * KT;
            uint32_t ka = ks_a[i & 1], va = vs_a[i & 1];
            #pragma unroll
            for (int r = 0; r < 2; r++) {
                int c = tid + r * 256;
                int dd = c >> 3, k8 = (c & 7) * 8;
                cpa(ka + (dd * KV_STR + k8) * 2, kb + (size_t)dd * SPA + t0 + k8);
                cpa(va + (dd * KV_STR + k8) * 2, vb + (size_t)dd * SPA + t0 + k8);
            }
            CP_COMMIT();
        }
        if (i + 1 < NTILE) {
            if (i + 2 < NTILE) { CP_WAIT1(); } else { CP_WAIT0(); }
            __syncthreads();
        }
    }

    // normalize + write f16: g_ao[b][h*64+dd][q0+qr]
    __half* ob = g_ao + ((size_t)b * CH + h * HD) * SPA + q0;
    #pragma unroll
    for (int rh = 0; rh < 2; rh++) {
        float inv = 1.0f / l[rh];
        int qr = w * 16 + rh * 8 + (lane >> 2);
        #pragma unroll
        for (int nt = 0; nt < 8; nt++) {
            int dd = nt * 8 + 2 * (lane & 3);
            ob[(size_t)dd * SPA + qr]       = __float2half(o_acc[nt][rh*2]   * inv);
            ob[(size_t)(dd + 1) * SPA + qr] = __float2half(o_acc[nt][rh*2+1] * inv);
        }
    }
}

// ---------------------------------------------------------------------------
extern "C" void kernel_launch(void* const* d_in, const int* in_sizes, int n_in,
                              void* d_out, int out_size) {
    const float* x      = (const float*)d_in[0];
    const float* gamma  = (const float*)d_in[1];
    const float* beta   = (const float*)d_in[2];
    const float* w_qkv  = (const float*)d_in[3];
    const float* b_qkv  = (const float*)d_in[4];
    const float* w_proj = (const float*)d_in[5];
    const float* b_proj = (const float*)d_in[6];
    float* out = (float*)d_out;

    __half *qkv_p, *ao_p;
    cudaGetSymbolAddress((void**)&qkv_p, g_qkv);
    cudaGetSymbolAddress((void**)&ao_p,  g_ao);

    cudaFuncSetAttribute(k_attn, cudaFuncAttributeMaxDynamicSharedMemorySize, SM_ATTN);

    // GroupNorm stats + coefficients
    k_gn_part <<<BATCH * NGRP * PARTS, 256>>>(x);
    k_gn_final<<<1, 1024>>>(gamma, beta);

    // QKV GEMM with fused GN (M = 768), f16 out
    {
        dim3 grid(SPA / 128, (3 * CH) / 128, BATCH);
        k_gemm<true, false, __half><<<grid, 256>>>(w_qkv, b_qkv, x, qkv_p,
                                                   nullptr, 3 * CH);
    }

    // f16 flash attention
    {
        dim3 grid(SPA / QT, BATCH * NH);
        k_attn<<<grid, 256, SM_ATTN>>>();
    }

    // Proj GEMM + residual (M = 256), fp32 out
    {
        dim3 grid(SPA / 128, CH / 128, BATCH);
        k_gemm<false, true, float><<<grid, 256>>>(w_proj, b_proj, ao_p, out, x, CH);
    }
}